// round 14
// baseline (speedup 1.0000x reference)
#include <cuda_runtime.h>
#include <cstddef>

typedef unsigned long long ull;

// ---------------------------------------------------------------------------
// Packed f32x2 helpers (Blackwell sm_100+)
// ---------------------------------------------------------------------------
__device__ __forceinline__ ull bcast2(float a) {
    ull r; asm("mov.b64 %0, {%1, %1};" : "=l"(r) : "f"(a)); return r;
}
__device__ __forceinline__ void unpack2(ull v, float& a, float& b) {
    asm("mov.b64 {%0, %1}, %2;" : "=f"(a), "=f"(b) : "l"(v));
}
__device__ __forceinline__ ull fma2(ull a, ull b, ull c) {
    ull d; asm("fma.rn.f32x2 %0, %1, %2, %3;" : "=l"(d) : "l"(a), "l"(b), "l"(c));
    return d;
}
__device__ __forceinline__ float ex2_fast(float x) {
    float r; asm("ex2.approx.f32 %0, %1;" : "=f"(r) : "f"(x)); return r;
}
__device__ __forceinline__ float rcp_fast(float x) {
    float r; asm("rcp.approx.f32 %0, %1;" : "=f"(r) : "f"(x)); return r;
}
// accurate tanh: 1 - 2/(e^{2z}+1) from ex2/rcp (~1e-6 rel err)
__device__ __forceinline__ float tanh_acc(float z) {
    float e = ex2_fast(2.8853900817779268f * z);   // e^{2z}
    float r = rcp_fast(e + 1.0f);
    return fmaf(-2.0f, r, 1.0f);
}

// ---------------------------------------------------------------------------
// Per-net smem layout (floats), stride 2944:
//   [0)    W1half [64][16]   [1024) b1[16]
//   [1040) W2 [16][16]       [1296) b2[16]
//   [1312) W3 [16][16]       [1568) b3[16]
//   [1584) W4 [16][16]       [1840) b4[16]
//   [1856) W5half [16][64]   [2880) b5half[64]
// Layer = t-net + s-net = 5888 floats = 23.5 KB.
// ---------------------------------------------------------------------------
#define TPB 128          // 64 t-threads + 64 s-threads
#define HT  64           // threads per side
#define R   4            // rows per thread; rows per block = 64*4 = 256
#define NET_STRIDE 2944

__device__ void load_net(float* L,
                         const float* W1, const float* b1,
                         const float* W2, const float* b2,
                         const float* W3, const float* b3,
                         const float* W4, const float* b4,
                         const float* W5, const float* b5,
                         int MOFF, int UOFF) {
    const int t = threadIdx.x;
    for (int idx = t; idx < 1024; idx += TPB) L[idx] = W1[(MOFF << 4) + idx];
    for (int idx = t; idx < 16;   idx += TPB) L[1024 + idx] = b1[idx];
    for (int idx = t; idx < 256;  idx += TPB) L[1040 + idx] = W2[idx];
    for (int idx = t; idx < 16;   idx += TPB) L[1296 + idx] = b2[idx];
    for (int idx = t; idx < 256;  idx += TPB) L[1312 + idx] = W3[idx];
    for (int idx = t; idx < 16;   idx += TPB) L[1568 + idx] = b3[idx];
    for (int idx = t; idx < 256;  idx += TPB) L[1584 + idx] = W4[idx];
    for (int idx = t; idx < 16;   idx += TPB) L[1840 + idx] = b4[idx];
    for (int idx = t; idx < 1024; idx += TPB)
        L[1856 + idx] = W5[(idx >> 6) * 128 + UOFF + (idx & 63)];
    for (int idx = t; idx < 64;   idx += TPB) L[2880 + idx] = b5[UOFF + idx];
}

// ---------------------------------------------------------------------------
// Hidden stack (64->16 then 3x 16->16) for ONE net over R rows.
// Masked half streamed from gmem/L2. copy: also copy masked half into y
// (warp-uniform flag; only the t-side on the first layer).
// ---------------------------------------------------------------------------
__device__ __forceinline__ void hidden_stack(const float* const (&xp)[R],
                                             float* const (&yp)[R],
                                             const bool (&ok)[R], int MOFF,
                                             bool copy,
                                             const float* __restrict__ swn,
                                             float (&h)[R][16]) {
    // layer 1: 64 -> 16
    {
        const ulonglong2* W = (const ulonglong2*)swn;
        const ull* b = (const ull*)(swn + 1024);
        ull a[R][8];
        #pragma unroll
        for (int i = 0; i < R; i++)
            #pragma unroll
            for (int j = 0; j < 8; j++) a[i][j] = b[j];
        #pragma unroll 1
        for (int q = 0; q < 16; q++) {
            float4 xv[R];
            #pragma unroll
            for (int i = 0; i < R; i++) {
                xv[i] = *(const float4*)(xp[i] + MOFF + 4 * q);
                if (copy && ok[i])
                    *(float4*)(yp[i] + MOFF + 4 * q) = xv[i];
            }
            #pragma unroll
            for (int kk = 0; kk < 4; kk++) {
                const int k = 4 * q + kk;
                ull xk[R];
                #pragma unroll
                for (int i = 0; i < R; i++)
                    xk[i] = bcast2(((const float*)&xv[i])[kk]);
                #pragma unroll
                for (int j = 0; j < 4; j++) {
                    ulonglong2 w = W[k * 4 + j];
                    #pragma unroll
                    for (int i = 0; i < R; i++) {
                        a[i][2 * j]     = fma2(xk[i], w.x, a[i][2 * j]);
                        a[i][2 * j + 1] = fma2(xk[i], w.y, a[i][2 * j + 1]);
                    }
                }
            }
        }
        #pragma unroll
        for (int i = 0; i < R; i++)
            #pragma unroll
            for (int j = 0; j < 8; j++) {
                float u, v; unpack2(a[i][j], u, v);
                h[i][2 * j]     = fmaxf(u, 0.0f);
                h[i][2 * j + 1] = fmaxf(v, 0.0f);
            }
    }
    // mids: 3x (16 -> 16)
    #pragma unroll 1
    for (int l = 0; l < 3; l++) {
        const ulonglong2* W = (const ulonglong2*)(swn + 1040 + l * 272);
        const ull* b = (const ull*)(swn + 1040 + l * 272 + 256);
        ull a[R][8];
        #pragma unroll
        for (int i = 0; i < R; i++)
            #pragma unroll
            for (int j = 0; j < 8; j++) a[i][j] = b[j];
        #pragma unroll
        for (int k = 0; k < 16; k++) {
            ull hk[R];
            #pragma unroll
            for (int i = 0; i < R; i++) hk[i] = bcast2(h[i][k]);
            #pragma unroll
            for (int j = 0; j < 4; j++) {
                ulonglong2 w = W[k * 4 + j];
                #pragma unroll
                for (int i = 0; i < R; i++) {
                    a[i][2 * j]     = fma2(hk[i], w.x, a[i][2 * j]);
                    a[i][2 * j + 1] = fma2(hk[i], w.y, a[i][2 * j + 1]);
                }
            }
        }
        #pragma unroll
        for (int i = 0; i < R; i++)
            #pragma unroll
            for (int j = 0; j < 8; j++) {
                float u, v; unpack2(a[i][j], u, v);
                h[i][2 * j]     = fmaxf(u, 0.0f);
                h[i][2 * j + 1] = fmaxf(v, 0.0f);
            }
    }
}

// ---------------------------------------------------------------------------
// One coupling layer. Block = 64 t-threads + 64 s-threads over the SAME
// 256 rows (R=4 each). Each thread runs ONE net (low register peak).
//   t-side: hT = hidden(x_m); y_u = x_u - t_head(hT)   [writes gmem]
//   __syncthreads()  (orders t-side global writes for the block)
//   s-side: hS = hidden(x_m); y_u *= exp(-tanh(s_head)); ld -= sum
// ---------------------------------------------------------------------------
template<int MOFF, bool FIRST>
__global__ void __launch_bounds__(TPB, 4)
layer_kernel(const float* __restrict__ x_in,
             const float* __restrict__ tW1, const float* __restrict__ tb1,
             const float* __restrict__ tW2, const float* __restrict__ tb2,
             const float* __restrict__ tW3, const float* __restrict__ tb3,
             const float* __restrict__ tW4, const float* __restrict__ tb4,
             const float* __restrict__ tW5, const float* __restrict__ tb5,
             const float* __restrict__ sW1, const float* __restrict__ sb1,
             const float* __restrict__ sW2, const float* __restrict__ sb2,
             const float* __restrict__ sW3, const float* __restrict__ sb3,
             const float* __restrict__ sW4, const float* __restrict__ sb4,
             const float* __restrict__ sW5, const float* __restrict__ sb5,
             float* __restrict__ y, float* __restrict__ ld_out, int B) {
    constexpr int UOFF = 64 - MOFF;
    __shared__ float sw[2 * NET_STRIDE];

    load_net(sw, tW1, tb1, tW2, tb2, tW3, tb3, tW4, tb4, tW5, tb5, MOFF, UOFF);
    load_net(sw + NET_STRIDE,
             sW1, sb1, sW2, sb2, sW3, sb3, sW4, sb4, sW5, sb5, MOFF, UOFF);
    __syncthreads();

    const int side = threadIdx.x >> 6;            // 0 = t-side, 1 = s-side
    const int wtid = threadIdx.x & 63;
    const int base = blockIdx.x * (HT * R) + wtid;

    const float* xp[R];
    float* yp[R];
    bool ok[R];
    #pragma unroll
    for (int i = 0; i < R; i++) {
        int row = base + i * HT;
        ok[i] = row < B;
        int rc = ok[i] ? row : 0;
        xp[i] = x_in + (size_t)rc * 128;
        yp[i] = y    + (size_t)rc * 128;
    }

    const float* swn = sw + side * NET_STRIDE;
    float h[R][16];
    hidden_stack(xp, yp, ok, MOFF, FIRST && side == 0, swn, h);

    const ulonglong2* W5 = (const ulonglong2*)(swn + 1856);
    const ull* b5 = (const ull*)(swn + 2880);

    // ---- t-side head: y_u = x_u - t, 8 chunks of 8 outputs ----
    if (side == 0) {
        #pragma unroll 1
        for (int c = 0; c < 8; c++) {
            ull o[R][4];
            #pragma unroll
            for (int i = 0; i < R; i++)
                #pragma unroll
                for (int u = 0; u < 4; u++) o[i][u] = b5[c * 4 + u];
            #pragma unroll
            for (int k = 0; k < 16; k++) {
                ull hk[R];
                #pragma unroll
                for (int i = 0; i < R; i++) hk[i] = bcast2(h[i][k]);
                #pragma unroll
                for (int j = 0; j < 2; j++) {
                    ulonglong2 w = W5[k * 16 + c * 2 + j];
                    #pragma unroll
                    for (int i = 0; i < R; i++) {
                        o[i][2 * j]     = fma2(hk[i], w.x, o[i][2 * j]);
                        o[i][2 * j + 1] = fma2(hk[i], w.y, o[i][2 * j + 1]);
                    }
                }
            }
            #pragma unroll
            for (int i = 0; i < R; i++) {
                if (!ok[i]) continue;
                float4 v0 = *(const float4*)(xp[i] + UOFF + c * 8);
                float4 v1 = *(const float4*)(xp[i] + UOFF + c * 8 + 4);
                float t0, t1, t2, t3, t4, t5, t6, t7;
                unpack2(o[i][0], t0, t1);
                unpack2(o[i][1], t2, t3);
                unpack2(o[i][2], t4, t5);
                unpack2(o[i][3], t6, t7);
                *(float4*)(yp[i] + UOFF + c * 8) =
                    make_float4(v0.x - t0, v0.y - t1, v0.z - t2, v0.w - t3);
                *(float4*)(yp[i] + UOFF + c * 8 + 4) =
                    make_float4(v1.x - t4, v1.y - t5, v1.z - t6, v1.w - t7);
            }
        }
    }

    __syncthreads();   // t-side writes to y are visible block-wide

    // ---- s-side head: y_u *= exp(-tanh(s)), 8 chunks; logdet ----
    if (side == 1) {
        float ldsum[R];
        #pragma unroll
        for (int i = 0; i < R; i++) ldsum[i] = 0.0f;

        #pragma unroll 1
        for (int c = 0; c < 8; c++) {
            ull o[R][4];
            #pragma unroll
            for (int i = 0; i < R; i++)
                #pragma unroll
                for (int u = 0; u < 4; u++) o[i][u] = b5[c * 4 + u];
            #pragma unroll
            for (int k = 0; k < 16; k++) {
                ull hk[R];
                #pragma unroll
                for (int i = 0; i < R; i++) hk[i] = bcast2(h[i][k]);
                #pragma unroll
                for (int j = 0; j < 2; j++) {
                    ulonglong2 w = W5[k * 16 + c * 2 + j];
                    #pragma unroll
                    for (int i = 0; i < R; i++) {
                        o[i][2 * j]     = fma2(hk[i], w.x, o[i][2 * j]);
                        o[i][2 * j + 1] = fma2(hk[i], w.y, o[i][2 * j + 1]);
                    }
                }
            }
            #pragma unroll
            for (int i = 0; i < R; i++) {
                float4 v0 = *(const float4*)(yp[i] + UOFF + c * 8);
                float4 v1 = *(const float4*)(yp[i] + UOFF + c * 8 + 4);
                float z[8], s[8];
                unpack2(o[i][0], z[0], z[1]);
                unpack2(o[i][1], z[2], z[3]);
                unpack2(o[i][2], z[4], z[5]);
                unpack2(o[i][3], z[6], z[7]);
                #pragma unroll
                for (int u = 0; u < 8; u++) {
                    s[u] = tanh_acc(z[u]);
                    ldsum[i] += s[u];
                }
                float4 r0 = make_float4(
                    v0.x * ex2_fast(-1.4426950408889634f * s[0]),
                    v0.y * ex2_fast(-1.4426950408889634f * s[1]),
                    v0.z * ex2_fast(-1.4426950408889634f * s[2]),
                    v0.w * ex2_fast(-1.4426950408889634f * s[3]));
                float4 r1 = make_float4(
                    v1.x * ex2_fast(-1.4426950408889634f * s[4]),
                    v1.y * ex2_fast(-1.4426950408889634f * s[5]),
                    v1.z * ex2_fast(-1.4426950408889634f * s[6]),
                    v1.w * ex2_fast(-1.4426950408889634f * s[7]));
                if (ok[i]) {
                    *(float4*)(yp[i] + UOFF + c * 8)     = r0;
                    *(float4*)(yp[i] + UOFF + c * 8 + 4) = r1;
                }
            }
        }

        #pragma unroll
        for (int i = 0; i < R; i++) {
            int row = base + i * HT;
            if (ok[i])
                ld_out[row] = (FIRST ? 0.0f : ld_out[row]) - ldsum[i];
        }
    }
}

// ---------------------------------------------------------------------------
// Harness entry: 6 sequential per-layer launches.
// Input order: x, masks, tW1,tb1,...,tW5,tb5, sW1,sb1,...,sW5,sb5
// Output: y [B,128] then logdet [B]
// ---------------------------------------------------------------------------
extern "C" void kernel_launch(void* const* d_in, const int* in_sizes, int n_in,
                              void* d_out, int out_size) {
    const float* x = (const float*)d_in[0];
    const float* P[20];
    for (int i = 0; i < 20; i++) P[i] = (const float*)d_in[2 + i];

    const int B = in_sizes[0] / 128;
    float* y  = (float*)d_out;
    float* ld = y + (size_t)B * 128;

    const int ROWS_PER_BLOCK = HT * R;   // 256
    const dim3 grid((B + ROWS_PER_BLOCK - 1) / ROWS_PER_BLOCK), block(TPB);

    // Processed layer i uses original layer p = 5 - i.
    // i even: masked half [0,64) (MOFF=0); i odd: MOFF=64.
#define ARGS(p)                                                              \
    P[0] + (p) * 2048, P[1] + (p) * 16,  P[2] + (p) * 256, P[3] + (p) * 16,  \
    P[4] + (p) * 256,  P[5] + (p) * 16,  P[6] + (p) * 256, P[7] + (p) * 16,  \
    P[8] + (p) * 2048, P[9] + (p) * 128,                                     \
    P[10] + (p) * 2048, P[11] + (p) * 16, P[12] + (p) * 256, P[13] + (p) * 16,\
    P[14] + (p) * 256,  P[15] + (p) * 16, P[16] + (p) * 256, P[17] + (p) * 16,\
    P[18] + (p) * 2048, P[19] + (p) * 128

    layer_kernel<0,  true ><<<grid, block>>>(x, ARGS(5), y, ld, B);
    layer_kernel<64, false><<<grid, block>>>(y, ARGS(4), y, ld, B);
    layer_kernel<0,  false><<<grid, block>>>(y, ARGS(3), y, ld, B);
    layer_kernel<64, false><<<grid, block>>>(y, ARGS(2), y, ld, B);
    layer_kernel<0,  false><<<grid, block>>>(y, ARGS(1), y, ld, B);
    layer_kernel<64, false><<<grid, block>>>(y, ARGS(0), y, ld, B);
#undef ARGS
}

// round 16
// speedup vs baseline: 1.7125x; 1.7125x over previous
#include <cuda_runtime.h>
#include <cstddef>

typedef unsigned long long ull;

// ---------------------------------------------------------------------------
// Packed f32x2 helpers (Blackwell sm_100+)
// ---------------------------------------------------------------------------
__device__ __forceinline__ ull bcast2(float a) {
    ull r; asm("mov.b64 %0, {%1, %1};" : "=l"(r) : "f"(a)); return r;
}
__device__ __forceinline__ void unpack2(ull v, float& a, float& b) {
    asm("mov.b64 {%0, %1}, %2;" : "=f"(a), "=f"(b) : "l"(v));
}
__device__ __forceinline__ ull fma2(ull a, ull b, ull c) {
    ull d; asm("fma.rn.f32x2 %0, %1, %2, %3;" : "=l"(d) : "l"(a), "l"(b), "l"(c));
    return d;
}
__device__ __forceinline__ float ex2_fast(float x) {
    float r; asm("ex2.approx.f32 %0, %1;" : "=f"(r) : "f"(x)); return r;
}
__device__ __forceinline__ float rcp_fast(float x) {
    float r; asm("rcp.approx.f32 %0, %1;" : "=f"(r) : "f"(x)); return r;
}
// accurate tanh: 1 - 2/(e^{2z}+1) from ex2/rcp (~1e-6 rel err)
__device__ __forceinline__ float tanh_acc(float z) {
    float e = ex2_fast(2.8853900817779268f * z);   // e^{2z}
    float r = rcp_fast(e + 1.0f);
    return fmaf(-2.0f, r, 1.0f);
}

// ---------------------------------------------------------------------------
// Transposed x scratch: XT[k][r] at g_xt[k*MB + r]. 128 x 131072 floats.
// (__device__ global array is the sanctioned scratch mechanism.)
// ---------------------------------------------------------------------------
#define MB 131072
__device__ float g_xt[128 * MB];

// ---------------------------------------------------------------------------
// Per-net smem layout (floats), stride 2944:
//   [0)    W1half [64][16]   [1024) b1[16]
//   [1040) W2 [16][16]       [1296) b2[16]
//   [1312) W3 [16][16]       [1568) b3[16]
//   [1584) W4 [16][16]       [1840) b4[16]
//   [1856) W5half [16][64]   [2880) b5half[64]
// ---------------------------------------------------------------------------
#define TPB 128
#define R   2              // rows per thread; 256 rows per block
#define NET_STRIDE 2944

__device__ void load_net(float* L,
                         const float* W1, const float* b1,
                         const float* W2, const float* b2,
                         const float* W3, const float* b3,
                         const float* W4, const float* b4,
                         const float* W5, const float* b5,
                         int MOFF, int UOFF) {
    const int t = threadIdx.x;
    for (int idx = t; idx < 1024; idx += TPB) L[idx] = W1[(MOFF << 4) + idx];
    for (int idx = t; idx < 16;   idx += TPB) L[1024 + idx] = b1[idx];
    for (int idx = t; idx < 256;  idx += TPB) L[1040 + idx] = W2[idx];
    for (int idx = t; idx < 16;   idx += TPB) L[1296 + idx] = b2[idx];
    for (int idx = t; idx < 256;  idx += TPB) L[1312 + idx] = W3[idx];
    for (int idx = t; idx < 16;   idx += TPB) L[1568 + idx] = b3[idx];
    for (int idx = t; idx < 256;  idx += TPB) L[1584 + idx] = W4[idx];
    for (int idx = t; idx < 16;   idx += TPB) L[1840 + idx] = b4[idx];
    for (int idx = t; idx < 1024; idx += TPB)
        L[1856 + idx] = W5[(idx >> 6) * 128 + UOFF + (idx & 63)];
    for (int idx = t; idx < 64;   idx += TPB) L[2880 + idx] = b5[UOFF + idx];
}

// ---------------------------------------------------------------------------
// Transpose kernels: x [B,128] <-> XT [128, MB].  32x32 smem tiles.
// block (32, 8); grid (B/32, 4).
// ---------------------------------------------------------------------------
__global__ void transpose_in(const float* __restrict__ x, int B) {
    __shared__ float t[32][33];
    const int r0 = blockIdx.x * 32;
    const int k0 = blockIdx.y * 32;
    const int tx = threadIdx.x, ty = threadIdx.y;
    #pragma unroll
    for (int i = 0; i < 4; i++) {
        int row = ty + i * 8;
        int r = r0 + row;
        if (r < B)
            t[row][tx] = x[(size_t)r * 128 + k0 + tx];
    }
    __syncthreads();
    #pragma unroll
    for (int i = 0; i < 4; i++) {
        int row = ty + i * 8;
        if (r0 + tx < B)
            g_xt[(size_t)(k0 + row) * MB + r0 + tx] = t[tx][row];
    }
}

__global__ void transpose_out(float* __restrict__ y, int B) {
    __shared__ float t[32][33];
    const int r0 = blockIdx.x * 32;
    const int k0 = blockIdx.y * 32;
    const int tx = threadIdx.x, ty = threadIdx.y;
    #pragma unroll
    for (int i = 0; i < 4; i++) {
        int row = ty + i * 8;
        if (r0 + tx < B)
            t[row][tx] = g_xt[(size_t)(k0 + row) * MB + r0 + tx];
    }
    __syncthreads();
    #pragma unroll
    for (int i = 0; i < 4; i++) {
        int row = ty + i * 8;
        int r = r0 + row;
        if (r < B)
            y[(size_t)r * 128 + k0 + tx] = t[tx][row];
    }
}

// ---------------------------------------------------------------------------
// One coupling layer on the TRANSPOSED layout (in-place on g_xt).
// All gmem accesses are coalesced (consecutive r within a warp).
// t & s nets interleaved in layer1/mids (shared x_m loads, 2 fma chains);
// heads fused per 8-output chunk: y_u = (x_u - t) * exp(-tanh(s)).
// ---------------------------------------------------------------------------
template<int MOFF, bool FIRST>
__global__ void __launch_bounds__(TPB, 3)
layer_t(float* __restrict__ ld_out, int B,
        const float* __restrict__ tW1, const float* __restrict__ tb1,
        const float* __restrict__ tW2, const float* __restrict__ tb2,
        const float* __restrict__ tW3, const float* __restrict__ tb3,
        const float* __restrict__ tW4, const float* __restrict__ tb4,
        const float* __restrict__ tW5, const float* __restrict__ tb5,
        const float* __restrict__ sW1, const float* __restrict__ sb1,
        const float* __restrict__ sW2, const float* __restrict__ sb2,
        const float* __restrict__ sW3, const float* __restrict__ sb3,
        const float* __restrict__ sW4, const float* __restrict__ sb4,
        const float* __restrict__ sW5, const float* __restrict__ sb5) {
    constexpr int UOFF = 64 - MOFF;
    __shared__ float sw[2 * NET_STRIDE];

    load_net(sw, tW1, tb1, tW2, tb2, tW3, tb3, tW4, tb4, tW5, tb5, MOFF, UOFF);
    load_net(sw + NET_STRIDE,
             sW1, sb1, sW2, sb2, sW3, sb3, sW4, sb4, sW5, sb5, MOFF, UOFF);
    __syncthreads();

    const int r = blockIdx.x * (TPB * R) + threadIdx.x;   // rows r, r+TPB
    if (r >= B) return;
    const bool ok1 = (r + TPB) < B;
    float* X = g_xt;

    // ---- layer 1 (64 -> 16), t & s interleaved over 2 rows ----
    float hT[R][16], hS[R][16];
    {
        const ulonglong2* WT = (const ulonglong2*)sw;
        const ulonglong2* WS = (const ulonglong2*)(sw + NET_STRIDE);
        const ull* bT = (const ull*)(sw + 1024);
        const ull* bS = (const ull*)(sw + NET_STRIDE + 1024);
        ull aT[R][8], aS[R][8];
        #pragma unroll
        for (int i = 0; i < R; i++)
            #pragma unroll
            for (int j = 0; j < 8; j++) { aT[i][j] = bT[j]; aS[i][j] = bS[j]; }
        #pragma unroll 8
        for (int k = 0; k < 64; k++) {
            const float* col = X + (size_t)(MOFF + k) * MB + r;
            ull xk[R];
            xk[0] = bcast2(col[0]);
            xk[1] = bcast2(ok1 ? col[TPB] : 0.0f);
            #pragma unroll
            for (int j = 0; j < 4; j++) {
                ulonglong2 wt = WT[k * 4 + j];
                #pragma unroll
                for (int i = 0; i < R; i++) {
                    aT[i][2 * j]     = fma2(xk[i], wt.x, aT[i][2 * j]);
                    aT[i][2 * j + 1] = fma2(xk[i], wt.y, aT[i][2 * j + 1]);
                }
                ulonglong2 ws = WS[k * 4 + j];
                #pragma unroll
                for (int i = 0; i < R; i++) {
                    aS[i][2 * j]     = fma2(xk[i], ws.x, aS[i][2 * j]);
                    aS[i][2 * j + 1] = fma2(xk[i], ws.y, aS[i][2 * j + 1]);
                }
            }
        }
        #pragma unroll
        for (int i = 0; i < R; i++)
            #pragma unroll
            for (int j = 0; j < 8; j++) {
                float u, v;
                unpack2(aT[i][j], u, v);
                hT[i][2 * j] = fmaxf(u, 0.0f); hT[i][2 * j + 1] = fmaxf(v, 0.0f);
                unpack2(aS[i][j], u, v);
                hS[i][2 * j] = fmaxf(u, 0.0f); hS[i][2 * j + 1] = fmaxf(v, 0.0f);
            }
    }

    // ---- mids 2..4 (16 -> 16), interleaved ----
    #pragma unroll 1
    for (int l = 0; l < 3; l++) {
        const float* baseT = sw + 1040 + l * 272;
        const ulonglong2* WT = (const ulonglong2*)baseT;
        const ulonglong2* WS = (const ulonglong2*)(baseT + NET_STRIDE);
        const ull* bT = (const ull*)(baseT + 256);
        const ull* bS = (const ull*)(baseT + NET_STRIDE + 256);
        ull aT[R][8], aS[R][8];
        #pragma unroll
        for (int i = 0; i < R; i++)
            #pragma unroll
            for (int j = 0; j < 8; j++) { aT[i][j] = bT[j]; aS[i][j] = bS[j]; }
        #pragma unroll
        for (int k = 0; k < 16; k++) {
            ull tk[R], sk[R];
            #pragma unroll
            for (int i = 0; i < R; i++) {
                tk[i] = bcast2(hT[i][k]);
                sk[i] = bcast2(hS[i][k]);
            }
            #pragma unroll
            for (int j = 0; j < 4; j++) {
                ulonglong2 wt = WT[k * 4 + j];
                #pragma unroll
                for (int i = 0; i < R; i++) {
                    aT[i][2 * j]     = fma2(tk[i], wt.x, aT[i][2 * j]);
                    aT[i][2 * j + 1] = fma2(tk[i], wt.y, aT[i][2 * j + 1]);
                }
                ulonglong2 ws = WS[k * 4 + j];
                #pragma unroll
                for (int i = 0; i < R; i++) {
                    aS[i][2 * j]     = fma2(sk[i], ws.x, aS[i][2 * j]);
                    aS[i][2 * j + 1] = fma2(sk[i], ws.y, aS[i][2 * j + 1]);
                }
            }
        }
        #pragma unroll
        for (int i = 0; i < R; i++)
            #pragma unroll
            for (int j = 0; j < 8; j++) {
                float u, v;
                unpack2(aT[i][j], u, v);
                hT[i][2 * j] = fmaxf(u, 0.0f); hT[i][2 * j + 1] = fmaxf(v, 0.0f);
                unpack2(aS[i][j], u, v);
                hS[i][2 * j] = fmaxf(u, 0.0f); hS[i][2 * j + 1] = fmaxf(v, 0.0f);
            }
    }

    // ---- heads fused: 8 chunks of 8 outputs; in-place update of x_u ----
    const ulonglong2* W5T = (const ulonglong2*)(sw + 1856);
    const ulonglong2* W5S = (const ulonglong2*)(sw + NET_STRIDE + 1856);
    const ull* b5T = (const ull*)(sw + 2880);
    const ull* b5S = (const ull*)(sw + NET_STRIDE + 2880);
    float ldsum[R];
    #pragma unroll
    for (int i = 0; i < R; i++) ldsum[i] = 0.0f;

    #pragma unroll 1
    for (int c = 0; c < 8; c++) {
        ull oT[R][4], oS[R][4];
        #pragma unroll
        for (int i = 0; i < R; i++)
            #pragma unroll
            for (int u = 0; u < 4; u++) {
                oT[i][u] = b5T[c * 4 + u];
                oS[i][u] = b5S[c * 4 + u];
            }
        #pragma unroll
        for (int k = 0; k < 16; k++) {
            ull tk[R], sk[R];
            #pragma unroll
            for (int i = 0; i < R; i++) {
                tk[i] = bcast2(hT[i][k]);
                sk[i] = bcast2(hS[i][k]);
            }
            #pragma unroll
            for (int j = 0; j < 2; j++) {
                ulonglong2 wt = W5T[k * 16 + c * 2 + j];
                #pragma unroll
                for (int i = 0; i < R; i++) {
                    oT[i][2 * j]     = fma2(tk[i], wt.x, oT[i][2 * j]);
                    oT[i][2 * j + 1] = fma2(tk[i], wt.y, oT[i][2 * j + 1]);
                }
                ulonglong2 ws = W5S[k * 16 + c * 2 + j];
                #pragma unroll
                for (int i = 0; i < R; i++) {
                    oS[i][2 * j]     = fma2(sk[i], ws.x, oS[i][2 * j]);
                    oS[i][2 * j + 1] = fma2(sk[i], ws.y, oS[i][2 * j + 1]);
                }
            }
        }
        // apply: x_u = (x_u - t) * exp(-tanh(z)); coalesced in-place update
        #pragma unroll
        for (int i = 0; i < R; i++) {
            if (i == 1 && !ok1) break;
            const int rr = r + i * TPB;
            float tvv[8], z[8];
            unpack2(oT[i][0], tvv[0], tvv[1]);
            unpack2(oT[i][1], tvv[2], tvv[3]);
            unpack2(oT[i][2], tvv[4], tvv[5]);
            unpack2(oT[i][3], tvv[6], tvv[7]);
            unpack2(oS[i][0], z[0], z[1]);
            unpack2(oS[i][1], z[2], z[3]);
            unpack2(oS[i][2], z[4], z[5]);
            unpack2(oS[i][3], z[6], z[7]);
            #pragma unroll
            for (int u = 0; u < 8; u++) {
                float* p = X + (size_t)(UOFF + c * 8 + u) * MB + rr;
                float s = tanh_acc(z[u]);
                ldsum[i] += s;
                float xv = *p;
                *p = (xv - tvv[u]) * ex2_fast(-1.4426950408889634f * s);
            }
        }
    }

    ld_out[r] = (FIRST ? 0.0f : ld_out[r]) - ldsum[0];
    if (ok1)
        ld_out[r + TPB] = (FIRST ? 0.0f : ld_out[r + TPB]) - ldsum[1];
}

// ---------------------------------------------------------------------------
// Harness entry: transpose_in + 6 layer kernels (in-place, transposed) +
// transpose_out. All graph-capturable, pointer-arg plumbing only.
// Input order: x, masks, tW1,tb1,...,tW5,tb5, sW1,sb1,...,sW5,sb5
// Output: y [B,128] then logdet [B]
// ---------------------------------------------------------------------------
extern "C" void kernel_launch(void* const* d_in, const int* in_sizes, int n_in,
                              void* d_out, int out_size) {
    const float* x = (const float*)d_in[0];
    const float* P[20];
    for (int i = 0; i < 20; i++) P[i] = (const float*)d_in[2 + i];

    const int B = in_sizes[0] / 128;
    float* y  = (float*)d_out;
    float* ld = y + (size_t)B * 128;

    const dim3 tgrid((B + 31) / 32, 4), tblock(32, 8);
    const dim3 lgrid((B + TPB * R - 1) / (TPB * R)), lblock(TPB);

    transpose_in<<<tgrid, tblock>>>(x, B);

    // Processed layer i uses original layer p = 5 - i.
    // i even: masked half [0,64) (MOFF=0); i odd: MOFF=64.
#define ARGS(p)                                                              \
    P[0] + (p) * 2048, P[1] + (p) * 16,  P[2] + (p) * 256, P[3] + (p) * 16,  \
    P[4] + (p) * 256,  P[5] + (p) * 16,  P[6] + (p) * 256, P[7] + (p) * 16,  \
    P[8] + (p) * 2048, P[9] + (p) * 128,                                     \
    P[10] + (p) * 2048, P[11] + (p) * 16, P[12] + (p) * 256, P[13] + (p) * 16,\
    P[14] + (p) * 256,  P[15] + (p) * 16, P[16] + (p) * 256, P[17] + (p) * 16,\
    P[18] + (p) * 2048, P[19] + (p) * 128

    layer_t<0,  true ><<<lgrid, lblock>>>(ld, B, ARGS(5));
    layer_t<64, false><<<lgrid, lblock>>>(ld, B, ARGS(4));
    layer_t<0,  false><<<lgrid, lblock>>>(ld, B, ARGS(3));
    layer_t<64, false><<<lgrid, lblock>>>(ld, B, ARGS(2));
    layer_t<0,  false><<<lgrid, lblock>>>(ld, B, ARGS(1));
    layer_t<64, false><<<lgrid, lblock>>>(ld, B, ARGS(0));
#undef ARGS

    transpose_out<<<tgrid, tblock>>>(y, B);
}

// round 17
// speedup vs baseline: 1.7231x; 1.0061x over previous
#include <cuda_runtime.h>
#include <cstddef>

typedef unsigned long long ull;

// ---------------------------------------------------------------------------
// Packed f32x2 helpers (Blackwell sm_100+)
// ---------------------------------------------------------------------------
__device__ __forceinline__ ull bcast2(float a) {
    ull r; asm("mov.b64 %0, {%1, %1};" : "=l"(r) : "f"(a)); return r;
}
__device__ __forceinline__ void unpack2(ull v, float& a, float& b) {
    asm("mov.b64 {%0, %1}, %2;" : "=f"(a), "=f"(b) : "l"(v));
}
__device__ __forceinline__ ull fma2(ull a, ull b, ull c) {
    ull d; asm("fma.rn.f32x2 %0, %1, %2, %3;" : "=l"(d) : "l"(a), "l"(b), "l"(c));
    return d;
}
__device__ __forceinline__ float ex2_fast(float x) {
    float r; asm("ex2.approx.f32 %0, %1;" : "=f"(r) : "f"(x)); return r;
}
__device__ __forceinline__ float rcp_fast(float x) {
    float r; asm("rcp.approx.f32 %0, %1;" : "=f"(r) : "f"(x)); return r;
}
// accurate tanh: 1 - 2/(e^{2z}+1) from ex2/rcp (~1e-6 rel err)
__device__ __forceinline__ float tanh_acc(float z) {
    float e = ex2_fast(2.8853900817779268f * z);   // e^{2z}
    float r = rcp_fast(e + 1.0f);
    return fmaf(-2.0f, r, 1.0f);
}

// ---------------------------------------------------------------------------
// Transposed x scratch: XT[k][r] at g_xt[k*MB + r]. 128 x 131072 floats.
// (__device__ global array is the sanctioned scratch mechanism.)
// ---------------------------------------------------------------------------
#define MB 131072
__device__ float g_xt[128 * MB];

// ---------------------------------------------------------------------------
// Per-net smem layout (floats), stride 2944:
//   [0)    W1half [64][16]   [1024) b1[16]
//   [1040) W2 [16][16]       [1296) b2[16]
//   [1312) W3 [16][16]       [1568) b3[16]
//   [1584) W4 [16][16]       [1840) b4[16]
//   [1856) W5half [16][64]   [2880) b5half[64]
// ---------------------------------------------------------------------------
#define TPB 128
#define NET_STRIDE 2944

__device__ void load_net(float* L,
                         const float* W1, const float* b1,
                         const float* W2, const float* b2,
                         const float* W3, const float* b3,
                         const float* W4, const float* b4,
                         const float* W5, const float* b5,
                         int MOFF, int UOFF) {
    const int t = threadIdx.x;
    for (int idx = t; idx < 1024; idx += TPB) L[idx] = W1[(MOFF << 4) + idx];
    for (int idx = t; idx < 16;   idx += TPB) L[1024 + idx] = b1[idx];
    for (int idx = t; idx < 256;  idx += TPB) L[1040 + idx] = W2[idx];
    for (int idx = t; idx < 16;   idx += TPB) L[1296 + idx] = b2[idx];
    for (int idx = t; idx < 256;  idx += TPB) L[1312 + idx] = W3[idx];
    for (int idx = t; idx < 16;   idx += TPB) L[1568 + idx] = b3[idx];
    for (int idx = t; idx < 256;  idx += TPB) L[1584 + idx] = W4[idx];
    for (int idx = t; idx < 16;   idx += TPB) L[1840 + idx] = b4[idx];
    for (int idx = t; idx < 1024; idx += TPB)
        L[1856 + idx] = W5[(idx >> 6) * 128 + UOFF + (idx & 63)];
    for (int idx = t; idx < 64;   idx += TPB) L[2880 + idx] = b5[UOFF + idx];
}

// ---------------------------------------------------------------------------
// Transpose kernels: x [B,128] <-> XT [128, MB].  32x32 smem tiles.
// block (32, 8); grid (B/32, 4).
// ---------------------------------------------------------------------------
__global__ void transpose_in(const float* __restrict__ x, int B) {
    __shared__ float t[32][33];
    const int r0 = blockIdx.x * 32;
    const int k0 = blockIdx.y * 32;
    const int tx = threadIdx.x, ty = threadIdx.y;
    #pragma unroll
    for (int i = 0; i < 4; i++) {
        int row = ty + i * 8;
        int r = r0 + row;
        if (r < B)
            t[row][tx] = x[(size_t)r * 128 + k0 + tx];
    }
    __syncthreads();
    #pragma unroll
    for (int i = 0; i < 4; i++) {
        int row = ty + i * 8;
        if (r0 + tx < B)
            g_xt[(size_t)(k0 + row) * MB + r0 + tx] = t[tx][row];
    }
}

__global__ void transpose_out(float* __restrict__ y, int B) {
    __shared__ float t[32][33];
    const int r0 = blockIdx.x * 32;
    const int k0 = blockIdx.y * 32;
    const int tx = threadIdx.x, ty = threadIdx.y;
    #pragma unroll
    for (int i = 0; i < 4; i++) {
        int row = ty + i * 8;
        if (r0 + tx < B)
            t[row][tx] = g_xt[(size_t)(k0 + row) * MB + r0 + tx];
    }
    __syncthreads();
    #pragma unroll
    for (int i = 0; i < 4; i++) {
        int row = ty + i * 8;
        int r = r0 + row;
        if (r < B)
            y[(size_t)r * 128 + k0 + tx] = t[tx][row];
    }
}

// ---------------------------------------------------------------------------
// One coupling layer on the TRANSPOSED layout (in-place on g_xt), R=1.
// All gmem accesses coalesced (warp = 32 consecutive rows).
// t & s interleaved throughout (shared x loads, 2 independent fma chains).
// Low register footprint (~100) so 5 blocks/SM fit -> 20 warps/SM.
// ---------------------------------------------------------------------------
template<int MOFF, bool FIRST>
__global__ void __launch_bounds__(TPB, 5)
layer_t(float* __restrict__ ld_out, int B,
        const float* __restrict__ tW1, const float* __restrict__ tb1,
        const float* __restrict__ tW2, const float* __restrict__ tb2,
        const float* __restrict__ tW3, const float* __restrict__ tb3,
        const float* __restrict__ tW4, const float* __restrict__ tb4,
        const float* __restrict__ tW5, const float* __restrict__ tb5,
        const float* __restrict__ sW1, const float* __restrict__ sb1,
        const float* __restrict__ sW2, const float* __restrict__ sb2,
        const float* __restrict__ sW3, const float* __restrict__ sb3,
        const float* __restrict__ sW4, const float* __restrict__ sb4,
        const float* __restrict__ sW5, const float* __restrict__ sb5) {
    constexpr int UOFF = 64 - MOFF;
    __shared__ float sw[2 * NET_STRIDE];

    load_net(sw, tW1, tb1, tW2, tb2, tW3, tb3, tW4, tb4, tW5, tb5, MOFF, UOFF);
    load_net(sw + NET_STRIDE,
             sW1, sb1, sW2, sb2, sW3, sb3, sW4, sb4, sW5, sb5, MOFF, UOFF);
    __syncthreads();

    const int r = blockIdx.x * TPB + threadIdx.x;
    if (r >= B) return;
    float* X = g_xt;

    // ---- layer 1 (64 -> 16), t & s interleaved ----
    float hT[16], hS[16];
    {
        const ulonglong2* WT = (const ulonglong2*)sw;
        const ulonglong2* WS = (const ulonglong2*)(sw + NET_STRIDE);
        const ull* bT = (const ull*)(sw + 1024);
        const ull* bS = (const ull*)(sw + NET_STRIDE + 1024);
        ull aT[8], aS[8];
        #pragma unroll
        for (int j = 0; j < 8; j++) { aT[j] = bT[j]; aS[j] = bS[j]; }
        #pragma unroll 8
        for (int k = 0; k < 64; k++) {
            ull xk = bcast2(X[(size_t)(MOFF + k) * MB + r]);
            #pragma unroll
            for (int j = 0; j < 4; j++) {
                ulonglong2 wt = WT[k * 4 + j];
                aT[2 * j]     = fma2(xk, wt.x, aT[2 * j]);
                aT[2 * j + 1] = fma2(xk, wt.y, aT[2 * j + 1]);
                ulonglong2 ws = WS[k * 4 + j];
                aS[2 * j]     = fma2(xk, ws.x, aS[2 * j]);
                aS[2 * j + 1] = fma2(xk, ws.y, aS[2 * j + 1]);
            }
        }
        #pragma unroll
        for (int j = 0; j < 8; j++) {
            float u, v;
            unpack2(aT[j], u, v);
            hT[2 * j] = fmaxf(u, 0.0f); hT[2 * j + 1] = fmaxf(v, 0.0f);
            unpack2(aS[j], u, v);
            hS[2 * j] = fmaxf(u, 0.0f); hS[2 * j + 1] = fmaxf(v, 0.0f);
        }
    }

    // ---- mids 2..4 (16 -> 16), interleaved ----
    #pragma unroll 1
    for (int l = 0; l < 3; l++) {
        const float* baseT = sw + 1040 + l * 272;
        const ulonglong2* WT = (const ulonglong2*)baseT;
        const ulonglong2* WS = (const ulonglong2*)(baseT + NET_STRIDE);
        const ull* bT = (const ull*)(baseT + 256);
        const ull* bS = (const ull*)(baseT + NET_STRIDE + 256);
        ull aT[8], aS[8];
        #pragma unroll
        for (int j = 0; j < 8; j++) { aT[j] = bT[j]; aS[j] = bS[j]; }
        #pragma unroll
        for (int k = 0; k < 16; k++) {
            ull tk = bcast2(hT[k]);
            ull sk = bcast2(hS[k]);
            #pragma unroll
            for (int j = 0; j < 4; j++) {
                ulonglong2 wt = WT[k * 4 + j];
                aT[2 * j]     = fma2(tk, wt.x, aT[2 * j]);
                aT[2 * j + 1] = fma2(tk, wt.y, aT[2 * j + 1]);
                ulonglong2 ws = WS[k * 4 + j];
                aS[2 * j]     = fma2(sk, ws.x, aS[2 * j]);
                aS[2 * j + 1] = fma2(sk, ws.y, aS[2 * j + 1]);
            }
        }
        #pragma unroll
        for (int j = 0; j < 8; j++) {
            float u, v;
            unpack2(aT[j], u, v);
            hT[2 * j] = fmaxf(u, 0.0f); hT[2 * j + 1] = fmaxf(v, 0.0f);
            unpack2(aS[j], u, v);
            hS[2 * j] = fmaxf(u, 0.0f); hS[2 * j + 1] = fmaxf(v, 0.0f);
        }
    }

    // ---- heads fused: 8 chunks of 8 outputs; in-place update of x_u ----
    const ulonglong2* W5T = (const ulonglong2*)(sw + 1856);
    const ulonglong2* W5S = (const ulonglong2*)(sw + NET_STRIDE + 1856);
    const ull* b5T = (const ull*)(sw + 2880);
    const ull* b5S = (const ull*)(sw + NET_STRIDE + 2880);
    float ldsum = 0.0f;

    #pragma unroll 1
    for (int c = 0; c < 8; c++) {
        ull oT[4], oS[4];
        #pragma unroll
        for (int u = 0; u < 4; u++) { oT[u] = b5T[c * 4 + u]; oS[u] = b5S[c * 4 + u]; }
        #pragma unroll
        for (int k = 0; k < 16; k++) {
            ull tk = bcast2(hT[k]);
            ull sk = bcast2(hS[k]);
            #pragma unroll
            for (int j = 0; j < 2; j++) {
                ulonglong2 wt = W5T[k * 16 + c * 2 + j];
                oT[2 * j]     = fma2(tk, wt.x, oT[2 * j]);
                oT[2 * j + 1] = fma2(tk, wt.y, oT[2 * j + 1]);
                ulonglong2 ws = W5S[k * 16 + c * 2 + j];
                oS[2 * j]     = fma2(sk, ws.x, oS[2 * j]);
                oS[2 * j + 1] = fma2(sk, ws.y, oS[2 * j + 1]);
            }
        }
        // apply: x_u = (x_u - t) * exp(-tanh(z)); coalesced in-place update
        float tvv[8], z[8];
        unpack2(oT[0], tvv[0], tvv[1]);
        unpack2(oT[1], tvv[2], tvv[3]);
        unpack2(oT[2], tvv[4], tvv[5]);
        unpack2(oT[3], tvv[6], tvv[7]);
        unpack2(oS[0], z[0], z[1]);
        unpack2(oS[1], z[2], z[3]);
        unpack2(oS[2], z[4], z[5]);
        unpack2(oS[3], z[6], z[7]);
        #pragma unroll
        for (int u = 0; u < 8; u++) {
            float* p = X + (size_t)(UOFF + c * 8 + u) * MB + r;
            float s = tanh_acc(z[u]);
            ldsum += s;
            float xv = *p;
            *p = (xv - tvv[u]) * ex2_fast(-1.4426950408889634f * s);
        }
    }

    ld_out[r] = (FIRST ? 0.0f : ld_out[r]) - ldsum;
}

// ---------------------------------------------------------------------------
// Harness entry: transpose_in + 6 layer kernels (in-place, transposed) +
// transpose_out. All graph-capturable, pointer-arg plumbing only.
// Input order: x, masks, tW1,tb1,...,tW5,tb5, sW1,sb1,...,sW5,sb5
// Output: y [B,128] then logdet [B]
// ---------------------------------------------------------------------------
extern "C" void kernel_launch(void* const* d_in, const int* in_sizes, int n_in,
                              void* d_out, int out_size) {
    const float* x = (const float*)d_in[0];
    const float* P[20];
    for (int i = 0; i < 20; i++) P[i] = (const float*)d_in[2 + i];

    const int B = in_sizes[0] / 128;
    float* y  = (float*)d_out;
    float* ld = y + (size_t)B * 128;

    const dim3 tgrid((B + 31) / 32, 4), tblock(32, 8);
    const dim3 lgrid((B + TPB - 1) / TPB), lblock(TPB);

    transpose_in<<<tgrid, tblock>>>(x, B);

    // Processed layer i uses original layer p = 5 - i.
    // i even: masked half [0,64) (MOFF=0); i odd: MOFF=64.
#define ARGS(p)                                                              \
    P[0] + (p) * 2048, P[1] + (p) * 16,  P[2] + (p) * 256, P[3] + (p) * 16,  \
    P[4] + (p) * 256,  P[5] + (p) * 16,  P[6] + (p) * 256, P[7] + (p) * 16,  \
    P[8] + (p) * 2048, P[9] + (p) * 128,                                     \
    P[10] + (p) * 2048, P[11] + (p) * 16, P[12] + (p) * 256, P[13] + (p) * 16,\
    P[14] + (p) * 256,  P[15] + (p) * 16, P[16] + (p) * 256, P[17] + (p) * 16,\
    P[18] + (p) * 2048, P[19] + (p) * 128

    layer_t<0,  true ><<<lgrid, lblock>>>(ld, B, ARGS(5));
    layer_t<64, false><<<lgrid, lblock>>>(ld, B, ARGS(4));
    layer_t<0,  false><<<lgrid, lblock>>>(ld, B, ARGS(3));
    layer_t<64, false><<<lgrid, lblock>>>(ld, B, ARGS(2));
    layer_t<0,  false><<<lgrid, lblock>>>(ld, B, ARGS(1));
    layer_t<64, false><<<lgrid, lblock>>>(ld, B, ARGS(0));
#undef ARGS

    transpose_out<<<tgrid, tblock>>>(y, B);
}